// round 10
// baseline (speedup 1.0000x reference)
#include <cuda_runtime.h>
#include <cstdint>

// CCN promotion layer, fused, warp-independent variant of the R5 design.
//   Each of the 8 warps owns rows {2w, 2w+1} of the c-dimension (a contiguous
//   6KB slice of the node's 48KB region): it zeroes its slice (12 STG.128 per
//   lane), then __syncwarp(), then lanes 0/1 overwrite the nonzeros of their
//   own rows. No block barrier -> warps retire independently.
// NOTE: default STG.128 only — __stcs measured 6.9 -> 4.9 TB/s (R6).
//
// tensors: [N, 3] f32 ; neigh: [N, 16] i32 (sorted per row)
// out = concat( promotions [N,16,16,16,3] f32 , new_parts [N,16] as f32 )
// promotions[n,c,a,b,s] = (nb[a]==nb[c] && nb[b]==nb[c]) ? tensors[nb[c]][s] : 0

static constexpr int D = 16;
static constexpr int F = 3;
static constexpr int PER_NODE     = D * D * D * F;     // 12288 floats
static constexpr int PER_NODE_V4  = PER_NODE / 4;      // 3072 float4
static constexpr int ROW_FLOATS   = D * D * F;         // 768 floats per c-row
static constexpr int THREADS      = 256;               // 8 warps
static constexpr int WARP_SLICE_V4 = 2 * ROW_FLOATS / 4;  // 384 float4 per warp
static constexpr int V4_PER_LANE  = WARP_SLICE_V4 / 32;   // 12

__global__ __launch_bounds__(THREADS, 8)
void ccn_fused_kernel(const float* __restrict__ tensors,
                      const int*   __restrict__ neigh,
                      float*       __restrict__ out,
                      float*       __restrict__ out_parts,
                      int N, int write_parts)
{
    const int n    = blockIdx.x;
    const int t    = threadIdx.x;
    const int w    = t >> 5;          // warp 0..7
    const int lane = t & 31;

    // ---- every warp loads the node's 16 neighbor ids (64B, L1-hit after
    //      the first warp) and builds the equality mask itself.
    int v = 0;
    unsigned m = 0u;
    if (lane < D) {
        v = neigh[n * D + lane];
        m = __match_any_sync(0x0000FFFFu, v) & 0xFFFFu;
    }

    // warp 0 also writes the new_parts tail
    if (w == 0 && lane < D && write_parts)
        out_parts[n * D + lane] = (float)v;   // exact: ids < 2^24

    // ---- owner lanes 0/1 fetch mask+feature for their row c = 2w + lane
    const int c = 2 * w + lane;                       // valid for lane < 2
    const unsigned mc = __shfl_sync(0xFFFFFFFFu, m, c & 15);
    const int      vc = __shfl_sync(0xFFFFFFFFu, v, c & 15);
    float f0 = 0.f, f1 = 0.f, f2 = 0.f;
    const bool owner = (lane < 2);
    if (owner) {
        f0 = tensors[vc * F + 0];
        f1 = tensors[vc * F + 1];
        f2 = tensors[vc * F + 2];
    }

    // ---- zero this warp's contiguous 6KB slice (rows 2w, 2w+1)
    float4* slice4 = reinterpret_cast<float4*>(out)
                   + (size_t)n * PER_NODE_V4 + w * WARP_SLICE_V4;
    const float4 z = make_float4(0.f, 0.f, 0.f, 0.f);
    #pragma unroll
    for (int k = 0; k < V4_PER_LANE; k++)
        slice4[lane + k * 32] = z;

    __syncwarp();   // order this warp's zeros before its own overwrites

    // ---- lanes 0/1 overwrite the nonzeros of their own row
    if (owner) {
        float* base = out + (size_t)n * PER_NODE + c * ROW_FLOATS;

        if (__popc(mc) == 1) {
            // common case: only (a,b) = (c,c)
            float* p = base + (c * D + c) * F;
            p[0] = f0; p[1] = f1; p[2] = f2;
        } else {
            unsigned ma = mc;
            while (ma) {
                int a = __ffs(ma) - 1; ma &= ma - 1;
                unsigned mb = mc;
                while (mb) {
                    int b = __ffs(mb) - 1; mb &= mb - 1;
                    float* p = base + (a * D + b) * F;
                    p[0] = f0; p[1] = f1; p[2] = f2;
                }
            }
        }
    }
}

extern "C" void kernel_launch(void* const* d_in, const int* in_sizes, int n_in,
                              void* d_out, int out_size)
{
    const float* tensors = (const float*)d_in[0];
    const int*   neigh   = (const int*)d_in[1];
    float*       out     = (float*)d_out;

    const int N = in_sizes[1] / D;
    const long long promo_elems = (long long)N * PER_NODE;
    const long long tail = (long long)out_size - promo_elems;
    const int write_parts = (tail == (long long)N * D) ? 1 : 0;
    float* out_parts = out + promo_elems;

    ccn_fused_kernel<<<N, THREADS>>>(tensors, neigh, out, out_parts,
                                     N, write_parts);
}